// round 1
// baseline (speedup 1.0000x reference)
#include <cuda_runtime.h>
#include <cuda_bf16.h>
#include <math.h>

// Problem constants
#define BATCH 8
#define C 512
#define NPIX 4096          // 64*64
#define HEADS 8
#define CH 64
#define QKV_M 1536
#define NSPLIT 16
#define SQRT_C 22.627416997969522f

// ---------------- scratch (device globals; no cudaMalloc allowed) ----------------
__device__ float g_w1[QKV_M * C];                        // norm_g-folded qkv weights
__device__ float g_s[BATCH * NPIX];                      // per-position rmsnorm scale
__device__ float g_qkv[(size_t)BATCH * QKV_M * NPIX];    // qkv activations
__device__ float g_kmax[BATCH * HEADS * CH];
__device__ float g_ksum[BATCH * HEADS * CH];
__device__ float g_part[(size_t)NSPLIT * BATCH * HEADS * CH * CH]; // split-K partials of k^T v
__device__ float g_attn[BATCH * HEADS * CH * CH];
__device__ float g_obuf[(size_t)BATCH * C * NPIX];       // attention output (channel-major)
__device__ float g_ffn[(size_t)BATCH * C * NPIX];        // ffn pre-norm

// ---------------- kernel: fold norm_g into qkv weights ----------------
__global__ void foldw_kernel(const float* __restrict__ qkv_w,
                             const float* __restrict__ norm_g,
                             float* __restrict__ w1) {
    int i = blockIdx.x * 256 + threadIdx.x;
    if (i < QKV_M * C) w1[i] = qkv_w[i] * norm_g[i & (C - 1)];
}

// ---------------- kernel: per-position L2 norm scale of x ----------------
__global__ __launch_bounds__(256) void norm_scale_kernel(const float* __restrict__ x,
                                                         float* __restrict__ s) {
    int blk = blockIdx.x;
    int b = blk >> 7;                 // / 128
    int p0 = (blk & 127) << 5;        // * 32
    int w = threadIdx.x >> 5, j = threadIdx.x & 31;
    const float* xb = x + (size_t)b * C * NPIX + p0 + j;
    float acc = 0.f;
    for (int c = w; c < C; c += 8) {
        float v = xb[(size_t)c * NPIX];
        acc += v * v;
    }
    __shared__ float red[8][32];
    red[w][j] = acc;
    __syncthreads();
    if (w == 0) {
        float t = 0.f;
        #pragma unroll
        for (int i = 0; i < 8; i++) t += red[i][j];
        float n = fmaxf(sqrtf(t), 1e-12f);
        s[b * NPIX + p0 + j] = SQRT_C / n;
    }
}

// ---------------- kernel: tiled fp32 GEMM ----------------
// C[b][m][n] = sum_k A[m][k] * B[b][k][n]   (K=512, N=4096)
// optional per-column scale (colscale[b][n]) and per-row bias[m]
__global__ __launch_bounds__(256) void sgemm_kernel(
    const float* __restrict__ A, const float* __restrict__ Ball,
    float* __restrict__ Call, int M,
    const float* __restrict__ colscale, const float* __restrict__ bias) {
    const int K = 512, N = 4096;
    int bz = blockIdx.z;
    const float* Bm = Ball + (size_t)bz * K * N;
    float* Cm = Call + (size_t)bz * M * N;
    int tM = blockIdx.y * 128;
    int tN = blockIdx.x * 128;

    __shared__ float As[8][128];
    __shared__ float Bs[8][128];

    int tid = threadIdx.x;
    int arow = tid >> 1;
    int acol = (tid & 1) << 2;
    int brow = tid >> 5;
    int bcol = (tid & 31) << 2;
    int ty = tid >> 4;
    int tx = tid & 15;

    const float* Aptr = A + (size_t)(tM + arow) * K + acol;
    const float* Bptr = Bm + (size_t)brow * N + tN + bcol;

    float acc[8][8];
    #pragma unroll
    for (int i = 0; i < 8; i++)
        #pragma unroll
        for (int j = 0; j < 8; j++) acc[i][j] = 0.f;

    for (int k0 = 0; k0 < K; k0 += 8) {
        float4 av = *(const float4*)(Aptr + k0);
        float4 bv = *(const float4*)(Bptr + (size_t)k0 * N);
        __syncthreads();
        As[acol + 0][arow] = av.x;
        As[acol + 1][arow] = av.y;
        As[acol + 2][arow] = av.z;
        As[acol + 3][arow] = av.w;
        *(float4*)&Bs[brow][bcol] = bv;
        __syncthreads();
        #pragma unroll
        for (int kk = 0; kk < 8; kk++) {
            float ar[8], br[8];
            *(float4*)&ar[0] = *(const float4*)&As[kk][ty * 4];
            *(float4*)&ar[4] = *(const float4*)&As[kk][64 + ty * 4];
            *(float4*)&br[0] = *(const float4*)&Bs[kk][tx * 4];
            *(float4*)&br[4] = *(const float4*)&Bs[kk][64 + tx * 4];
            #pragma unroll
            for (int i = 0; i < 8; i++)
                #pragma unroll
                for (int j = 0; j < 8; j++)
                    acc[i][j] = fmaf(ar[i], br[j], acc[i][j]);
        }
    }

    #pragma unroll
    for (int i = 0; i < 8; i++) {
        int r = tM + ((i < 4) ? (ty * 4 + i) : (64 + ty * 4 + i - 4));
        float bb = bias ? bias[r] : 0.f;
        float* crow = Cm + (size_t)r * N;
        // first 4 columns (contiguous)
        {
            int c0 = tN + tx * 4;
            float4 v;
            float s0 = colscale ? colscale[(size_t)bz * N + c0 + 0] : 1.f;
            float s1 = colscale ? colscale[(size_t)bz * N + c0 + 1] : 1.f;
            float s2 = colscale ? colscale[(size_t)bz * N + c0 + 2] : 1.f;
            float s3 = colscale ? colscale[(size_t)bz * N + c0 + 3] : 1.f;
            v.x = (acc[i][0] + bb) * s0;
            v.y = (acc[i][1] + bb) * s1;
            v.z = (acc[i][2] + bb) * s2;
            v.w = (acc[i][3] + bb) * s3;
            *(float4*)(crow + c0) = v;
        }
        // second 4 columns
        {
            int c0 = tN + 64 + tx * 4;
            float4 v;
            float s0 = colscale ? colscale[(size_t)bz * N + c0 + 0] : 1.f;
            float s1 = colscale ? colscale[(size_t)bz * N + c0 + 1] : 1.f;
            float s2 = colscale ? colscale[(size_t)bz * N + c0 + 2] : 1.f;
            float s3 = colscale ? colscale[(size_t)bz * N + c0 + 3] : 1.f;
            v.x = (acc[i][4] + bb) * s0;
            v.y = (acc[i][5] + bb) * s1;
            v.z = (acc[i][6] + bb) * s2;
            v.w = (acc[i][7] + bb) * s3;
            *(float4*)(crow + c0) = v;
        }
    }
}

// ---------------- kernel: k softmax stats (max, sum-exp over n) ----------------
__global__ __launch_bounds__(256) void kstats_kernel(const float* __restrict__ qkv,
                                                     float* __restrict__ kmax,
                                                     float* __restrict__ ksum) {
    int idx = blockIdx.x;            // b*512 + (h*64+c)
    int b = idx >> 9, hc = idx & 511;
    const float* row = qkv + ((size_t)b * QKV_M + 512 + hc) * NPIX;
    int tid = threadIdx.x;
    __shared__ float red[256];
    float m = -1e30f;
    for (int n = tid; n < NPIX; n += 256) m = fmaxf(m, row[n]);
    red[tid] = m;
    __syncthreads();
    for (int st = 128; st > 0; st >>= 1) {
        if (tid < st) red[tid] = fmaxf(red[tid], red[tid + st]);
        __syncthreads();
    }
    m = red[0];
    float s = 0.f;
    for (int n = tid; n < NPIX; n += 256) s += __expf(row[n] - m);
    __syncthreads();
    red[tid] = s;
    __syncthreads();
    for (int st = 128; st > 0; st >>= 1) {
        if (tid < st) red[tid] += red[tid + st];
        __syncthreads();
    }
    if (tid == 0) {
        kmax[idx] = m;
        ksum[idx] = red[0];
    }
}

// ---------------- kernel: split-K  attn_part[split][bh][c][d] = sum_n exp(k-max) * v ----------------
__global__ __launch_bounds__(256) void kv_kernel(const float* __restrict__ qkv,
                                                 const float* __restrict__ kmax,
                                                 float* __restrict__ part) {
    int bh = blockIdx.y;
    int b = bh >> 3, h = bh & 7;
    int n0 = blockIdx.x * 256;       // split id = blockIdx.x, 4096/16 = 256 each
    const float* kb = qkv + ((size_t)b * QKV_M + 512 + (size_t)h * CH) * NPIX;
    const float* vb = qkv + ((size_t)b * QKV_M + 1024 + (size_t)h * CH) * NPIX;
    __shared__ float Ks[64][33];
    __shared__ float Vs[64][33];
    __shared__ float km[64];
    int tid = threadIdx.x;
    if (tid < 64) km[tid] = kmax[bh * 64 + tid];
    float acc[4][4] = {};
    int ty = tid >> 4, tx = tid & 15;
    for (int nn = 0; nn < 256; nn += 32) {
        __syncthreads();
        #pragma unroll
        for (int l = 0; l < 2; l++) {
            int idx4 = tid + l * 256;          // 0..511
            int r = idx4 >> 3, c4 = (idx4 & 7) << 2;
            float4 kv = *(const float4*)&kb[(size_t)r * NPIX + n0 + nn + c4];
            float mm = km[r];
            Ks[r][c4 + 0] = __expf(kv.x - mm);
            Ks[r][c4 + 1] = __expf(kv.y - mm);
            Ks[r][c4 + 2] = __expf(kv.z - mm);
            Ks[r][c4 + 3] = __expf(kv.w - mm);
            float4 vv = *(const float4*)&vb[(size_t)r * NPIX + n0 + nn + c4];
            Vs[r][c4 + 0] = vv.x;
            Vs[r][c4 + 1] = vv.y;
            Vs[r][c4 + 2] = vv.z;
            Vs[r][c4 + 3] = vv.w;
        }
        __syncthreads();
        #pragma unroll 8
        for (int p = 0; p < 32; p++) {
            float kr[4], vr[4];
            #pragma unroll
            for (int i = 0; i < 4; i++) kr[i] = Ks[ty * 4 + i][p];
            #pragma unroll
            for (int j = 0; j < 4; j++) vr[j] = Vs[tx * 4 + j][p];
            #pragma unroll
            for (int i = 0; i < 4; i++)
                #pragma unroll
                for (int j = 0; j < 4; j++)
                    acc[i][j] = fmaf(kr[i], vr[j], acc[i][j]);
        }
    }
    float* pp = part + ((size_t)blockIdx.x * 64 + bh) * (CH * CH);
    #pragma unroll
    for (int i = 0; i < 4; i++)
        #pragma unroll
        for (int j = 0; j < 4; j++)
            pp[(ty * 4 + i) * 64 + tx * 4 + j] = acc[i][j];
}

// ---------------- kernel: combine partials, divide by ksum, fold SCALE ----------------
__global__ void attn_finalize(const float* __restrict__ part,
                              const float* __restrict__ ksum,
                              float* __restrict__ attn) {
    int idx = blockIdx.x * 256 + threadIdx.x;   // 0..262143
    int bh = idx >> 12;
    int cd = idx & 4095;
    int c = cd >> 6;
    float s = 0.f;
    #pragma unroll
    for (int sp = 0; sp < NSPLIT; sp++)
        s += part[((size_t)sp * 64 + bh) * 4096 + cd];
    attn[idx] = s / ksum[bh * 64 + c] * 0.125f;   // SCALE = 64^-0.5 folded here
}

// ---------------- kernel: q softmax (over ch) + out = qs @ attn ----------------
__global__ __launch_bounds__(256) void qattn_kernel(const float* __restrict__ qkv,
                                                    const float* __restrict__ attn,
                                                    float* __restrict__ outp) {
    int bh = blockIdx.y;             // 0..63
    int b = bh >> 3, h = bh & 7;
    int n0 = blockIdx.x * 32;        // 32 positions per block
    __shared__ float at[64][64];
    __shared__ float qs[32][65];     // [n][c]
    __shared__ float os[64][33];     // [d][n]
    int tid = threadIdx.x;

    // load attn tile
    #pragma unroll
    for (int i = 0; i < 4; i++) {
        int idx4 = tid + i * 256;    // 0..1023
        int r = idx4 >> 4, c4 = (idx4 & 15) << 2;
        *(float4*)&at[r][c4] = *(const float4*)&attn[((size_t)bh * 64 + r) * 64 + c4];
    }
    // load q transposed: qs[n][c]
    const float* qbase = qkv + ((size_t)b * QKV_M + (size_t)h * CH) * NPIX + n0;
    #pragma unroll
    for (int l = 0; l < 2; l++) {
        int idx4 = tid + l * 256;    // 0..511 (32*64/4)
        int c = idx4 >> 3;           // 0..63
        int n4 = (idx4 & 7) << 2;    // 0..28
        float4 v = *(const float4*)&qbase[(size_t)c * NPIX + n4];
        qs[n4 + 0][c] = v.x;
        qs[n4 + 1][c] = v.y;
        qs[n4 + 2][c] = v.z;
        qs[n4 + 3][c] = v.w;
    }
    __syncthreads();

    int w = tid >> 5, lane = tid & 31;
    for (int it = 0; it < 4; it++) {
        int nl = w * 4 + it;
        float q0 = qs[nl][lane], q1 = qs[nl][lane + 32];
        float m = fmaxf(q0, q1);
        #pragma unroll
        for (int o = 16; o > 0; o >>= 1) m = fmaxf(m, __shfl_xor_sync(0xffffffffu, m, o));
        float e0 = __expf(q0 - m), e1 = __expf(q1 - m);
        float ssum = e0 + e1;
        #pragma unroll
        for (int o = 16; o > 0; o >>= 1) ssum += __shfl_xor_sync(0xffffffffu, ssum, o);
        float inv = 1.0f / ssum;
        float a0 = 0.f, a1 = 0.f;
        #pragma unroll
        for (int c = 0; c < 32; c++) {
            float ec = __shfl_sync(0xffffffffu, e0, c);
            a0 = fmaf(ec, at[c][lane], a0);
            a1 = fmaf(ec, at[c][lane + 32], a1);
        }
        #pragma unroll
        for (int c = 0; c < 32; c++) {
            float ec = __shfl_sync(0xffffffffu, e1, c);
            a0 = fmaf(ec, at[c + 32][lane], a0);
            a1 = fmaf(ec, at[c + 32][lane + 32], a1);
        }
        os[lane][nl] = a0 * inv;
        os[lane + 32][nl] = a1 * inv;
    }
    __syncthreads();

    float* obase = outp + ((size_t)b * C + (size_t)h * CH) * NPIX + n0;
    #pragma unroll
    for (int i = 0; i < 8; i++) {
        int idx = tid + i * 256;     // 0..2047
        int d = idx >> 5, nl = idx & 31;
        obase[(size_t)d * NPIX + nl] = os[d][nl];
    }
}

// ---------------- kernel: final rmsnorm + residual ----------------
__global__ __launch_bounds__(256) void final_kernel(const float* __restrict__ t,
                                                    const float* __restrict__ x,
                                                    const float* __restrict__ g2,
                                                    float* __restrict__ outp) {
    int blk = blockIdx.x;
    int b = blk >> 7;
    int p0 = (blk & 127) << 5;
    int w = threadIdx.x >> 5, j = threadIdx.x & 31;
    const float* tb = t + (size_t)b * C * NPIX + p0 + j;
    float acc = 0.f;
    for (int c = w; c < C; c += 8) {
        float v = tb[(size_t)c * NPIX];
        acc += v * v;
    }
    __shared__ float red[8][32];
    __shared__ float inv[32];
    red[w][j] = acc;
    __syncthreads();
    if (w == 0) {
        float s = 0.f;
        #pragma unroll
        for (int i = 0; i < 8; i++) s += red[i][j];
        float n = fmaxf(sqrtf(s), 1e-12f);
        inv[j] = SQRT_C / n;
    }
    __syncthreads();
    float iv = inv[j];
    const float* xb = x + (size_t)b * C * NPIX + p0 + j;
    float* ob = outp + (size_t)b * C * NPIX + p0 + j;
    for (int c = w; c < C; c += 8) {
        float v = tb[(size_t)c * NPIX];
        ob[(size_t)c * NPIX] = v * iv * g2[c] + xb[(size_t)c * NPIX];
    }
}

// ---------------- launch ----------------
extern "C" void kernel_launch(void* const* d_in, const int* in_sizes, int n_in,
                              void* d_out, int out_size) {
    (void)in_sizes; (void)n_in; (void)out_size;
    const float* x         = (const float*)d_in[0];
    const float* norm_g    = (const float*)d_in[1];
    const float* qkv_w     = (const float*)d_in[2];
    const float* ffn_w     = (const float*)d_in[3];
    const float* ffn_b     = (const float*)d_in[4];
    const float* ffn_gn    = (const float*)d_in[5];
    float* out = (float*)d_out;

    float *w1, *s, *qkv, *kmax, *ksum, *part, *attn, *obuf, *ffn;
    cudaGetSymbolAddress((void**)&w1,   g_w1);
    cudaGetSymbolAddress((void**)&s,    g_s);
    cudaGetSymbolAddress((void**)&qkv,  g_qkv);
    cudaGetSymbolAddress((void**)&kmax, g_kmax);
    cudaGetSymbolAddress((void**)&ksum, g_ksum);
    cudaGetSymbolAddress((void**)&part, g_part);
    cudaGetSymbolAddress((void**)&attn, g_attn);
    cudaGetSymbolAddress((void**)&obuf, g_obuf);
    cudaGetSymbolAddress((void**)&ffn,  g_ffn);

    foldw_kernel<<<(QKV_M * C + 255) / 256, 256>>>(qkv_w, norm_g, w1);
    norm_scale_kernel<<<BATCH * (NPIX / 32), 256>>>(x, s);
    sgemm_kernel<<<dim3(32, 12, BATCH), 256>>>(w1, x, qkv, QKV_M, s, nullptr);
    kstats_kernel<<<BATCH * 512, 256>>>(qkv, kmax, ksum);
    kv_kernel<<<dim3(NSPLIT, BATCH * HEADS), 256>>>(qkv, kmax, part);
    attn_finalize<<<(BATCH * HEADS * CH * CH) / 256, 256>>>(part, ksum, attn);
    qattn_kernel<<<dim3(NPIX / 32, BATCH * HEADS), 256>>>(qkv, attn, obuf);
    sgemm_kernel<<<dim3(32, 4, BATCH), 256>>>(ffn_w, obuf, ffn, C, nullptr, ffn_b);
    final_kernel<<<BATCH * (NPIX / 32), 256>>>(ffn, x, ffn_gn, out);
}

// round 3
// speedup vs baseline: 1.0073x; 1.0073x over previous
#include <cuda_runtime.h>
#include <cuda_bf16.h>
#include <math.h>
#include <stdint.h>

#define BATCH 8
#define C 512
#define NPIX 4096
#define HEADS 8
#define CH 64
#define QKV_M 1536
#define NSPLIT 16
#define SQRT_C 22.627416997969522f

// GEMM tiling
#define BM 128
#define BN 128
#define BK 32
#define KST 40        // smem row stride in bf16 (80 bytes, conflict-free for ldmatrix)

// ---------------- device scratch ----------------
__device__ __nv_bfloat16 g_whi[QKV_M * C];
__device__ __nv_bfloat16 g_wlo[QKV_M * C];
__device__ __nv_bfloat16 g_fhi[C * C];
__device__ __nv_bfloat16 g_flo[C * C];
__device__ float g_s[BATCH * NPIX];
__device__ __nv_bfloat16 g_xhi[(size_t)BATCH * NPIX * C];
__device__ __nv_bfloat16 g_xlo[(size_t)BATCH * NPIX * C];
__device__ float g_qkv[(size_t)BATCH * QKV_M * NPIX];
__device__ float g_kmax[BATCH * HEADS * CH];
__device__ float g_ksum[BATCH * HEADS * CH];
__device__ float g_part[(size_t)NSPLIT * BATCH * HEADS * CH * CH];
__device__ float g_attn[BATCH * HEADS * CH * CH];
__device__ __nv_bfloat16 g_ohi[(size_t)BATCH * NPIX * C];
__device__ __nv_bfloat16 g_olo[(size_t)BATCH * NPIX * C];
__device__ float g_ffn[(size_t)BATCH * C * NPIX];

__device__ __forceinline__ uint32_t smem_u32(const void* p) {
    uint32_t a;
    asm("{ .reg .u64 t; cvta.to.shared.u64 t, %1; cvt.u32.u64 %0, t; }" : "=r"(a) : "l"(p));
    return a;
}

// ---------------- weight split ----------------
__global__ void wsplit_kernel(const float* __restrict__ w, const float* __restrict__ g,
                              __nv_bfloat16* __restrict__ hi, __nv_bfloat16* __restrict__ lo,
                              int total) {
    int i = blockIdx.x * 256 + threadIdx.x;
    if (i >= total) return;
    float v = w[i];
    if (g) v *= g[i & (C - 1)];
    __nv_bfloat16 h = __float2bfloat16_rn(v);
    hi[i] = h;
    lo[i] = __float2bfloat16_rn(v - __bfloat162float(h));
}

// ---------------- rmsnorm scale ----------------
__global__ __launch_bounds__(256) void norm_scale_kernel(const float* __restrict__ x,
                                                         float* __restrict__ s) {
    int blk = blockIdx.x;
    int b = blk >> 7;
    int p0 = (blk & 127) << 5;
    int w = threadIdx.x >> 5, j = threadIdx.x & 31;
    const float* xb = x + (size_t)b * C * NPIX + p0 + j;
    float acc = 0.f;
    for (int c = w; c < C; c += 8) {
        float v = xb[(size_t)c * NPIX];
        acc += v * v;
    }
    __shared__ float red[8][32];
    red[w][j] = acc;
    __syncthreads();
    if (w == 0) {
        float t = 0.f;
        #pragma unroll
        for (int i = 0; i < 8; i++) t += red[i][j];
        float n = fmaxf(sqrtf(t), 1e-12f);
        s[b * NPIX + p0 + j] = SQRT_C / n;
    }
}

// ---------------- transpose + scale + split ----------------
__global__ __launch_bounds__(256) void xtrans_kernel(const float* __restrict__ x,
                                                     const float* __restrict__ s,
                                                     __nv_bfloat16* __restrict__ xhi,
                                                     __nv_bfloat16* __restrict__ xlo) {
    int c0 = blockIdx.x * 64;
    int n0 = blockIdx.y * 32;
    int b = blockIdx.z;
    int tid = threadIdx.x;
    __shared__ float ts[64][33];
    #pragma unroll
    for (int l = 0; l < 8; l++) {
        int i = l * 256 + tid;
        int cc = i >> 5, nn = i & 31;
        ts[cc][nn] = x[((size_t)b * C + c0 + cc) * NPIX + n0 + nn];
    }
    __syncthreads();
    #pragma unroll
    for (int l = 0; l < 4; l++) {
        int p = l * 256 + tid;
        int nn = p >> 5;
        int cp = p & 31;
        int c = cp * 2;
        float sc = s[b * NPIX + n0 + nn];
        float v0 = ts[c][nn] * sc;
        float v1 = ts[c + 1][nn] * sc;
        __nv_bfloat16 h0 = __float2bfloat16_rn(v0);
        __nv_bfloat16 h1 = __float2bfloat16_rn(v1);
        size_t off = ((size_t)b * NPIX + n0 + nn) * C + c0 + c;
        __nv_bfloat162 hp; hp.x = h0; hp.y = h1;
        *(__nv_bfloat162*)(xhi + off) = hp;
        __nv_bfloat162 lp;
        lp.x = __float2bfloat16_rn(v0 - __bfloat162float(h0));
        lp.y = __float2bfloat16_rn(v1 - __bfloat162float(h1));
        *(__nv_bfloat162*)(xlo + off) = lp;
    }
}

// ---------------- mma.sync bf16 3-split GEMM ----------------
// Cout[b][m][n] = fp32( sum_c A[m][c] * B[b][n][c] ), A/B split hi/lo
__global__ __launch_bounds__(256, 2) void hgemm_kernel(
    const __nv_bfloat16* __restrict__ Ahi, const __nv_bfloat16* __restrict__ Alo,
    const __nv_bfloat16* __restrict__ Bhi, const __nv_bfloat16* __restrict__ Blo,
    float* __restrict__ Cout, int M, const float* __restrict__ bias) {
    __shared__ __align__(16) __nv_bfloat16 As[2][BM * KST];
    __shared__ __align__(16) __nv_bfloat16 Bs[2][BM * KST];

    int tid = threadIdx.x, wid = tid >> 5, lane = tid & 31;
    int m0 = blockIdx.y * BM, n0 = blockIdx.x * BN, b = blockIdx.z;
    const __nv_bfloat16* Bh = Bhi + (size_t)b * NPIX * C;
    const __nv_bfloat16* Bl = Blo + (size_t)b * NPIX * C;
    float* Cb = Cout + (size_t)b * M * NPIX;

    int wm = (wid >> 2) * 64;     // warp m offset within tile
    int wn = (wid & 3) * 32;      // warp n offset

    // load slots: slot s -> row s>>2 (0..127), kchunk s&3 (8 bf16 each)
    int r0_ = tid >> 2, kc_ = tid & 3;

    float acc[4][4][4];
    #pragma unroll
    for (int i = 0; i < 4; i++)
        #pragma unroll
        for (int j = 0; j < 4; j++)
            #pragma unroll
            for (int q = 0; q < 4; q++) acc[i][j][q] = 0.f;

    uint32_t sA = smem_u32(&As[0][0]);
    uint32_t sB = smem_u32(&Bs[0][0]);
    const uint32_t bufBytes = BM * KST * 2;

    uint4 arg[2], brg[2];

    // ---- prologue: load chunk 0 (phase 0: Ahi, Bhi; k0 = 0)
    {
        arg[0] = *(const uint4*)(Ahi + (size_t)(m0 + r0_) * C + kc_ * 8);
        arg[1] = *(const uint4*)(Ahi + (size_t)(m0 + 64 + r0_) * C + kc_ * 8);
        brg[0] = *(const uint4*)(Bh + (size_t)(n0 + r0_) * C + kc_ * 8);
        brg[1] = *(const uint4*)(Bh + (size_t)(n0 + 64 + r0_) * C + kc_ * 8);
        *(uint4*)(&As[0][r0_ * KST + kc_ * 8]) = arg[0];
        *(uint4*)(&As[0][(64 + r0_) * KST + kc_ * 8]) = arg[1];
        *(uint4*)(&Bs[0][r0_ * KST + kc_ * 8]) = brg[0];
        *(uint4*)(&Bs[0][(64 + r0_) * KST + kc_ * 8]) = brg[1];
    }
    __syncthreads();

    for (int ch = 0; ch < 48; ch++) {
        // prefetch next chunk
        if (ch < 47) {
            int nc = ch + 1;
            int phase = nc >> 4;
            int k0 = (nc & 15) << 5;
            const __nv_bfloat16* Asrc = (phase == 2) ? Alo : Ahi;
            const __nv_bfloat16* Bsrc = (phase == 1) ? Bl : Bh;
            arg[0] = *(const uint4*)(Asrc + (size_t)(m0 + r0_) * C + k0 + kc_ * 8);
            arg[1] = *(const uint4*)(Asrc + (size_t)(m0 + 64 + r0_) * C + k0 + kc_ * 8);
            brg[0] = *(const uint4*)(Bsrc + (size_t)(n0 + r0_) * C + k0 + kc_ * 8);
            brg[1] = *(const uint4*)(Bsrc + (size_t)(n0 + 64 + r0_) * C + k0 + kc_ * 8);
        }

        // compute on buffer ch&1
        uint32_t aBase = sA + (ch & 1) * bufBytes;
        uint32_t bBase = sB + (ch & 1) * bufBytes;
        #pragma unroll
        for (int ks = 0; ks < 2; ks++) {
            uint32_t af[4][4];
            uint32_t bf[2][4];
            #pragma unroll
            for (int mt = 0; mt < 4; mt++) {
                uint32_t addr = aBase +
                    ((wm + mt * 16 + (lane & 15)) * KST + ks * 16 + (lane >> 4) * 8) * 2;
                asm volatile("ldmatrix.sync.aligned.m8n8.x4.shared.b16 {%0,%1,%2,%3}, [%4];"
                             : "=r"(af[mt][0]), "=r"(af[mt][1]), "=r"(af[mt][2]), "=r"(af[mt][3])
                             : "r"(addr));
            }
            #pragma unroll
            for (int np = 0; np < 2; np++) {
                uint32_t addr = bBase +
                    ((wn + np * 16 + (lane & 15)) * KST + ks * 16 + (lane >> 4) * 8) * 2;
                asm volatile("ldmatrix.sync.aligned.m8n8.x4.shared.b16 {%0,%1,%2,%3}, [%4];"
                             : "=r"(bf[np][0]), "=r"(bf[np][1]), "=r"(bf[np][2]), "=r"(bf[np][3])
                             : "r"(addr));
            }
            #pragma unroll
            for (int mt = 0; mt < 4; mt++) {
                #pragma unroll
                for (int nt = 0; nt < 4; nt++) {
                    uint32_t b0 = bf[nt >> 1][(nt & 1)];
                    uint32_t b1 = bf[nt >> 1][(nt & 1) + 2];
                    asm volatile(
                        "mma.sync.aligned.m16n8k16.row.col.f32.bf16.bf16.f32 "
                        "{%0,%1,%2,%3}, {%4,%5,%6,%7}, {%8,%9}, {%0,%1,%2,%3};"
                        : "+f"(acc[mt][nt][0]), "+f"(acc[mt][nt][1]),
                          "+f"(acc[mt][nt][2]), "+f"(acc[mt][nt][3])
                        : "r"(af[mt][0]), "r"(af[mt][1]), "r"(af[mt][2]), "r"(af[mt][3]),
                          "r"(b0), "r"(b1));
                }
            }
        }

        if (ch < 47) {
            int nb = (ch + 1) & 1;
            *(uint4*)(&As[nb][r0_ * KST + kc_ * 8]) = arg[0];
            *(uint4*)(&As[nb][(64 + r0_) * KST + kc_ * 8]) = arg[1];
            *(uint4*)(&Bs[nb][r0_ * KST + kc_ * 8]) = brg[0];
            *(uint4*)(&Bs[nb][(64 + r0_) * KST + kc_ * 8]) = brg[1];
            __syncthreads();
        }
    }

    // epilogue
    #pragma unroll
    for (int mt = 0; mt < 4; mt++) {
        int r = m0 + wm + mt * 16 + (lane >> 2);
        float b0v = bias ? bias[r] : 0.f;
        float b1v = bias ? bias[r + 8] : 0.f;
        #pragma unroll
        for (int nt = 0; nt < 4; nt++) {
            int cn = n0 + wn + nt * 8 + (lane & 3) * 2;
            float2 v0, v1;
            v0.x = acc[mt][nt][0] + b0v;
            v0.y = acc[mt][nt][1] + b0v;
            v1.x = acc[mt][nt][2] + b1v;
            v1.y = acc[mt][nt][3] + b1v;
            *(float2*)(Cb + (size_t)r * NPIX + cn) = v0;
            *(float2*)(Cb + (size_t)(r + 8) * NPIX + cn) = v1;
        }
    }
}

// ---------------- k softmax stats ----------------
__global__ __launch_bounds__(256) void kstats_kernel(const float* __restrict__ qkv,
                                                     float* __restrict__ kmax,
                                                     float* __restrict__ ksum) {
    int idx = blockIdx.x;
    int b = idx >> 9, hc = idx & 511;
    const float* row = qkv + ((size_t)b * QKV_M + 512 + hc) * NPIX;
    int tid = threadIdx.x;
    __shared__ float red[256];
    float m = -1e30f;
    for (int n = tid; n < NPIX; n += 256) m = fmaxf(m, row[n]);
    red[tid] = m;
    __syncthreads();
    for (int st = 128; st > 0; st >>= 1) {
        if (tid < st) red[tid] = fmaxf(red[tid], red[tid + st]);
        __syncthreads();
    }
    m = red[0];
    float s = 0.f;
    for (int n = tid; n < NPIX; n += 256) s += __expf(row[n] - m);
    __syncthreads();
    red[tid] = s;
    __syncthreads();
    for (int st = 128; st > 0; st >>= 1) {
        if (tid < st) red[tid] += red[tid + st];
        __syncthreads();
    }
    if (tid == 0) {
        kmax[idx] = m;
        ksum[idx] = red[0];
    }
}

// ---------------- split-K k^T v ----------------
__global__ __launch_bounds__(256) void kv_kernel(const float* __restrict__ qkv,
                                                 const float* __restrict__ kmax,
                                                 float* __restrict__ part) {
    int bh = blockIdx.y;
    int b = bh >> 3, h = bh & 7;
    int n0 = blockIdx.x * 256;
    const float* kb = qkv + ((size_t)b * QKV_M + 512 + (size_t)h * CH) * NPIX;
    const float* vb = qkv + ((size_t)b * QKV_M + 1024 + (size_t)h * CH) * NPIX;
    __shared__ float Ks[64][33];
    __shared__ float Vs[64][33];
    __shared__ float km[64];
    int tid = threadIdx.x;
    if (tid < 64) km[tid] = kmax[bh * 64 + tid];
    float acc[4][4] = {};
    int ty = tid >> 4, tx = tid & 15;
    for (int nn = 0; nn < 256; nn += 32) {
        __syncthreads();
        #pragma unroll
        for (int l = 0; l < 2; l++) {
            int idx4 = tid + l * 256;
            int r = idx4 >> 3, c4 = (idx4 & 7) << 2;
            float4 kv = *(const float4*)&kb[(size_t)r * NPIX + n0 + nn + c4];
            float mm = km[r];
            Ks[r][c4 + 0] = __expf(kv.x - mm);
            Ks[r][c4 + 1] = __expf(kv.y - mm);
            Ks[r][c4 + 2] = __expf(kv.z - mm);
            Ks[r][c4 + 3] = __expf(kv.w - mm);
            float4 vv = *(const float4*)&vb[(size_t)r * NPIX + n0 + nn + c4];
            Vs[r][c4 + 0] = vv.x;
            Vs[r][c4 + 1] = vv.y;
            Vs[r][c4 + 2] = vv.z;
            Vs[r][c4 + 3] = vv.w;
        }
        __syncthreads();
        #pragma unroll 8
        for (int p = 0; p < 32; p++) {
            float kr[4], vr[4];
            #pragma unroll
            for (int i = 0; i < 4; i++) kr[i] = Ks[ty * 4 + i][p];
            #pragma unroll
            for (int j = 0; j < 4; j++) vr[j] = Vs[tx * 4 + j][p];
            #pragma unroll
            for (int i = 0; i < 4; i++)
                #pragma unroll
                for (int j = 0; j < 4; j++)
                    acc[i][j] = fmaf(kr[i], vr[j], acc[i][j]);
        }
    }
    float* pp = part + ((size_t)blockIdx.x * 64 + bh) * (CH * CH);
    #pragma unroll
    for (int i = 0; i < 4; i++)
        #pragma unroll
        for (int j = 0; j < 4; j++)
            pp[(ty * 4 + i) * 64 + tx * 4 + j] = acc[i][j];
}

// ---------------- combine partials ----------------
__global__ void attn_finalize(const float* __restrict__ part,
                              const float* __restrict__ ksum,
                              float* __restrict__ attn) {
    int idx = blockIdx.x * 256 + threadIdx.x;
    int bh = idx >> 12;
    int cd = idx & 4095;
    int c = cd >> 6;
    float s = 0.f;
    #pragma unroll
    for (int sp = 0; sp < NSPLIT; sp++)
        s += part[((size_t)sp * 64 + bh) * 4096 + cd];
    attn[idx] = s / ksum[bh * 64 + c] * 0.125f;
}

// ---------------- q softmax + out = qs @ attn -> bf16 hi/lo transposed ----------------
__global__ __launch_bounds__(256) void qattn_kernel(const float* __restrict__ qkv,
                                                    const float* __restrict__ attn,
                                                    __nv_bfloat16* __restrict__ ohi,
                                                    __nv_bfloat16* __restrict__ olo) {
    int bh = blockIdx.y;
    int b = bh >> 3, h = bh & 7;
    int n0 = blockIdx.x * 32;
    __shared__ float at[64][64];
    __shared__ float qs[32][65];
    __shared__ float os[64][33];
    int tid = threadIdx.x;

    #pragma unroll
    for (int i = 0; i < 4; i++) {
        int idx4 = tid + i * 256;
        int r = idx4 >> 4, c4 = (idx4 & 15) << 2;
        *(float4*)&at[r][c4] = *(const float4*)&attn[((size_t)bh * 64 + r) * 64 + c4];
    }
    const float* qbase = qkv + ((size_t)b * QKV_M + (size_t)h * CH) * NPIX + n0;
    #pragma unroll
    for (int l = 0; l < 2; l++) {
        int idx4 = tid + l * 256;
        int c = idx4 >> 3;
        int n4 = (idx4 & 7) << 2;
        float4 v = *(const float4*)&qbase[(size_t)c * NPIX + n4];
        qs[n4 + 0][c] = v.x;
        qs[n4 + 1][c] = v.y;
        qs[n4 + 2][c] = v.z;
        qs[n4 + 3][c] = v.w;
    }
    __syncthreads();

    int w = tid >> 5, lane = tid & 31;
    for (int it = 0; it < 4; it++) {
        int nl = w * 4 + it;
        float q0 = qs[nl][lane], q1 = qs[nl][lane + 32];
        float m = fmaxf(q0, q1);
        #pragma unroll
        for (int o = 16; o > 0; o >>= 1) m = fmaxf(m, __shfl_xor_sync(0xffffffffu, m, o));
        float e0 = __expf(q0 - m), e1 = __expf(q1 - m);
        float ssum = e0 + e1;
        #pragma unroll
        for (int o = 16; o > 0; o >>= 1) ssum += __shfl_xor_sync(0xffffffffu, ssum, o);
        float inv = 1.0f / ssum;
        float a0 = 0.f, a1 = 0.f;
        #pragma unroll
        for (int c = 0; c < 32; c++) {
            float ec = __shfl_sync(0xffffffffu, e0, c);
            a0 = fmaf(ec, at[c][lane], a0);
            a1 = fmaf(ec, at[c][lane + 32], a1);
        }
        #pragma unroll
        for (int c = 0; c < 32; c++) {
            float ec = __shfl_sync(0xffffffffu, e1, c);
            a0 = fmaf(ec, at[c + 32][lane], a0);
            a1 = fmaf(ec, at[c + 32][lane + 32], a1);
        }
        os[lane][nl] = a0 * inv;
        os[lane + 32][nl] = a1 * inv;
    }
    __syncthreads();

    size_t obase = ((size_t)b * NPIX + n0) * C + (size_t)h * CH;
    #pragma unroll
    for (int l = 0; l < 4; l++) {
        int p = tid + l * 256;
        int nl = p >> 5;
        int dp = p & 31;
        int d = dp * 2;
        float v0 = os[d][nl], v1 = os[d + 1][nl];
        __nv_bfloat16 h0 = __float2bfloat16_rn(v0);
        __nv_bfloat16 h1 = __float2bfloat16_rn(v1);
        size_t off = obase + (size_t)nl * C + d;
        __nv_bfloat162 hp; hp.x = h0; hp.y = h1;
        *(__nv_bfloat162*)(ohi + off) = hp;
        __nv_bfloat162 lp;
        lp.x = __float2bfloat16_rn(v0 - __bfloat162float(h0));
        lp.y = __float2bfloat16_rn(v1 - __bfloat162float(h1));
        *(__nv_bfloat162*)(olo + off) = lp;
    }
}

// ---------------- final rmsnorm + residual ----------------
__global__ __launch_bounds__(256) void final_kernel(const float* __restrict__ t,
                                                    const float* __restrict__ x,
                                                    const float* __restrict__ g2,
                                                    float* __restrict__ outp) {
    int blk = blockIdx.x;
    int b = blk >> 7;
    int p0 = (blk & 127) << 5;
    int w = threadIdx.x >> 5, j = threadIdx.x & 31;
    const float* tb = t + (size_t)b * C * NPIX + p0 + j;
    float acc = 0.f;
    for (int c = w; c < C; c += 8) {
        float v = tb[(size_t)c * NPIX];
        acc += v * v;
    }
    __shared__ float red[8][32];
    __shared__ float inv[32];
    red[w][j] = acc;
    __syncthreads();
    if (w == 0) {
        float s = 0.f;
        #pragma unroll
        for (int i = 0; i < 8; i++) s += red[i][j];
        float n = fmaxf(sqrtf(s), 1e-12f);
        inv[j] = SQRT_C / n;
    }
    __syncthreads();
    float iv = inv[j];
    const float* xb = x + (size_t)b * C * NPIX + p0 + j;
    float* ob = outp + (size_t)b * C * NPIX + p0 + j;
    for (int c = w; c < C; c += 8) {
        float v = tb[(size_t)c * NPIX];
        ob[(size_t)c * NPIX] = v * iv * g2[c] + xb[(size_t)c * NPIX];
    }
}

// ---------------- launch ----------------
extern "C" void kernel_launch(void* const* d_in, const int* in_sizes, int n_in,
                              void* d_out, int out_size) {
    (void)in_sizes; (void)n_in; (void)out_size;
    const float* x      = (const float*)d_in[0];
    const float* norm_g = (const float*)d_in[1];
    const float* qkv_w  = (const float*)d_in[2];
    const float* ffn_w  = (const float*)d_in[3];
    const float* ffn_b  = (const float*)d_in[4];
    const float* ffn_gn = (const float*)d_in[5];
    float* out = (float*)d_out;

    __nv_bfloat16 *whi, *wlo, *fhi, *flo, *xhi, *xlo, *ohi, *olo;
    float *s, *qkv, *kmax, *ksum, *part, *attn, *ffn;
    cudaGetSymbolAddress((void**)&whi, g_whi);
    cudaGetSymbolAddress((void**)&wlo, g_wlo);
    cudaGetSymbolAddress((void**)&fhi, g_fhi);
    cudaGetSymbolAddress((void**)&flo, g_flo);
    cudaGetSymbolAddress((void**)&s, g_s);
    cudaGetSymbolAddress((void**)&xhi, g_xhi);
    cudaGetSymbolAddress((void**)&xlo, g_xlo);
    cudaGetSymbolAddress((void**)&qkv, g_qkv);
    cudaGetSymbolAddress((void**)&kmax, g_kmax);
    cudaGetSymbolAddress((void**)&ksum, g_ksum);
    cudaGetSymbolAddress((void**)&part, g_part);
    cudaGetSymbolAddress((void**)&attn, g_attn);
    cudaGetSymbolAddress((void**)&ohi, g_ohi);
    cudaGetSymbolAddress((void**)&olo, g_olo);
    cudaGetSymbolAddress((void**)&ffn, g_ffn);

    wsplit_kernel<<<(QKV_M * C) / 256, 256>>>(qkv_w, norm_g, whi, wlo, QKV_M * C);
    wsplit_kernel<<<(C * C) / 256, 256>>>(ffn_w, nullptr, fhi, flo, C * C);
    norm_scale_kernel<<<BATCH * (NPIX / 32), 256>>>(x, s);
    xtrans_kernel<<<dim3(C / 64, NPIX / 32, BATCH), 256>>>(x, s, xhi, xlo);
    hgemm_kernel<<<dim3(32, 12, BATCH), 256>>>(whi, wlo, xhi, xlo, qkv, QKV_M, nullptr);
    kstats_kernel<<<BATCH * 512, 256>>>(qkv, kmax, ksum);
    kv_kernel<<<dim3(NSPLIT, BATCH * HEADS), 256>>>(qkv, kmax, part);
    attn_finalize<<<(BATCH * HEADS * CH * CH) / 256, 256>>>(part, ksum, attn);
    qattn_kernel<<<dim3(NPIX / 32, BATCH * HEADS), 256>>>(qkv, attn, ohi, olo);
    hgemm_kernel<<<dim3(32, 4, BATCH), 256>>>(fhi, flo, ohi, olo, ffn, C, ffn_b);
    final_kernel<<<BATCH * (NPIX / 32), 256>>>(ffn, x, ffn_gn, out);
}

// round 4
// speedup vs baseline: 1.0313x; 1.0239x over previous
#include <cuda_runtime.h>
#include <cuda_bf16.h>
#include <math.h>
#include <stdint.h>

#define BATCH 8
#define C 512
#define NPIX 4096
#define HEADS 8
#define CH 64
#define QKV_M 1536
#define NSPLIT 16
#define SQRT_C 22.627416997969522f

// GEMM tiling
#define BM 128
#define BN 128
#define BK 32
#define KST 40                 // smem row stride in bf16 (80B: 16B-aligned, ldmatrix conflict-free)
#define GTHREADS 512
#define STAGE_BYTES (2 * BM * KST * 2)   // A tile + B tile per stage = 20480
#define GEMM_SMEM (3 * STAGE_BYTES)      // 61440

// ---------------- device scratch ----------------
__device__ __nv_bfloat16 g_whi[QKV_M * C];
__device__ __nv_bfloat16 g_wlo[QKV_M * C];
__device__ __nv_bfloat16 g_fhi[C * C];
__device__ __nv_bfloat16 g_flo[C * C];
__device__ float g_s[BATCH * NPIX];
__device__ __nv_bfloat16 g_xhi[(size_t)BATCH * NPIX * C];
__device__ __nv_bfloat16 g_xlo[(size_t)BATCH * NPIX * C];
__device__ float g_qkv[(size_t)BATCH * QKV_M * NPIX];
__device__ float g_kmax[BATCH * HEADS * CH];
__device__ float g_ksum[BATCH * HEADS * CH];
__device__ float g_part[(size_t)NSPLIT * BATCH * HEADS * CH * CH];
__device__ float g_attn[BATCH * HEADS * CH * CH];
__device__ __nv_bfloat16 g_ohi[(size_t)BATCH * NPIX * C];
__device__ __nv_bfloat16 g_olo[(size_t)BATCH * NPIX * C];
__device__ float g_ffn[(size_t)BATCH * C * NPIX];

__device__ __forceinline__ uint32_t smem_u32(const void* p) {
    uint32_t a;
    asm("{ .reg .u64 t; cvta.to.shared.u64 t, %1; cvt.u32.u64 %0, t; }" : "=r"(a) : "l"(p));
    return a;
}

// ---------------- weight split ----------------
__global__ void wsplit_kernel(const float* __restrict__ w, const float* __restrict__ g,
                              __nv_bfloat16* __restrict__ hi, __nv_bfloat16* __restrict__ lo,
                              int total) {
    int i = blockIdx.x * 256 + threadIdx.x;
    if (i >= total) return;
    float v = w[i];
    if (g) v *= g[i & (C - 1)];
    __nv_bfloat16 h = __float2bfloat16_rn(v);
    hi[i] = h;
    lo[i] = __float2bfloat16_rn(v - __bfloat162float(h));
}

// ---------------- rmsnorm scale ----------------
__global__ __launch_bounds__(256) void norm_scale_kernel(const float* __restrict__ x,
                                                         float* __restrict__ s) {
    int blk = blockIdx.x;
    int b = blk >> 7;
    int p0 = (blk & 127) << 5;
    int w = threadIdx.x >> 5, j = threadIdx.x & 31;
    const float* xb = x + (size_t)b * C * NPIX + p0 + j;
    float acc = 0.f;
    for (int c = w; c < C; c += 8) {
        float v = xb[(size_t)c * NPIX];
        acc += v * v;
    }
    __shared__ float red[8][32];
    red[w][j] = acc;
    __syncthreads();
    if (w == 0) {
        float t = 0.f;
        #pragma unroll
        for (int i = 0; i < 8; i++) t += red[i][j];
        float n = fmaxf(sqrtf(t), 1e-12f);
        s[b * NPIX + p0 + j] = SQRT_C / n;
    }
}

// ---------------- transpose + scale + split ----------------
__global__ __launch_bounds__(256) void xtrans_kernel(const float* __restrict__ x,
                                                     const float* __restrict__ s,
                                                     __nv_bfloat16* __restrict__ xhi,
                                                     __nv_bfloat16* __restrict__ xlo) {
    int c0 = blockIdx.x * 64;
    int n0 = blockIdx.y * 32;
    int b = blockIdx.z;
    int tid = threadIdx.x;
    __shared__ float ts[64][33];
    #pragma unroll
    for (int l = 0; l < 8; l++) {
        int i = l * 256 + tid;
        int cc = i >> 5, nn = i & 31;
        ts[cc][nn] = x[((size_t)b * C + c0 + cc) * NPIX + n0 + nn];
    }
    __syncthreads();
    #pragma unroll
    for (int l = 0; l < 4; l++) {
        int p = l * 256 + tid;
        int nn = p >> 5;
        int cp = p & 31;
        int c = cp * 2;
        float sc = s[b * NPIX + n0 + nn];
        float v0 = ts[c][nn] * sc;
        float v1 = ts[c + 1][nn] * sc;
        __nv_bfloat16 h0 = __float2bfloat16_rn(v0);
        __nv_bfloat16 h1 = __float2bfloat16_rn(v1);
        size_t off = ((size_t)b * NPIX + n0 + nn) * C + c0 + c;
        __nv_bfloat162 hp; hp.x = h0; hp.y = h1;
        *(__nv_bfloat162*)(xhi + off) = hp;
        __nv_bfloat162 lp;
        lp.x = __float2bfloat16_rn(v0 - __bfloat162float(h0));
        lp.y = __float2bfloat16_rn(v1 - __bfloat162float(h1));
        *(__nv_bfloat162*)(xlo + off) = lp;
    }
}

// ---------------- mma.sync bf16 3-split GEMM (cp.async, 3-stage) ----------------
__global__ __launch_bounds__(GTHREADS, 1) void hgemm_kernel(
    const __nv_bfloat16* __restrict__ Ahi, const __nv_bfloat16* __restrict__ Alo,
    const __nv_bfloat16* __restrict__ Bhi, const __nv_bfloat16* __restrict__ Blo,
    float* __restrict__ Cout, int M, const float* __restrict__ bias) {
    extern __shared__ __align__(16) char smem[];
    uint32_t sbase = smem_u32(smem);

    int tid = threadIdx.x, wid = tid >> 5, lane = tid & 31;
    int m0 = blockIdx.y * BM, n0 = blockIdx.x * BN, b = blockIdx.z;
    const __nv_bfloat16* Bh = Bhi + (size_t)b * NPIX * C;
    const __nv_bfloat16* Bl = Blo + (size_t)b * NPIX * C;
    float* Cb = Cout + (size_t)b * M * NPIX;

    int wm = (wid >> 2) * 32;     // warp m offset
    int wn = (wid & 3) * 32;      // warp n offset

    // cp.async slot: thread tid -> row tid>>2 (0..127), kseg tid&3 (8 bf16)
    int rr = tid >> 2, kc = tid & 3;
    uint32_t dstA = (rr * KST + kc * 8) * 2;
    uint32_t dstB = STAGE_BYTES / 2 + dstA;   // B half of stage

    float acc[2][4][4];
    #pragma unroll
    for (int i = 0; i < 2; i++)
        #pragma unroll
        for (int j = 0; j < 4; j++)
            #pragma unroll
            for (int q = 0; q < 4; q++) acc[i][j][q] = 0.f;

    // issue chunk ch into stage st (always commits a group)
    auto issue = [&](int ch, int st) {
        if (ch < 48) {
            int phase = ch >> 4;
            int k0 = (ch & 15) << 5;
            const __nv_bfloat16* Asrc = (phase == 2) ? Alo : Ahi;
            const __nv_bfloat16* Bsrc = (phase == 1) ? Bl : Bh;
            uint32_t da = sbase + st * STAGE_BYTES + dstA;
            uint32_t db = sbase + st * STAGE_BYTES + dstB;
            const __nv_bfloat16* ga = Asrc + (size_t)(m0 + rr) * C + k0 + kc * 8;
            const __nv_bfloat16* gb = Bsrc + (size_t)(n0 + rr) * C + k0 + kc * 8;
            asm volatile("cp.async.cg.shared.global [%0], [%1], 16;" :: "r"(da), "l"(ga));
            asm volatile("cp.async.cg.shared.global [%0], [%1], 16;" :: "r"(db), "l"(gb));
        }
        asm volatile("cp.async.commit_group;" ::: "memory");
    };

    issue(0, 0);
    issue(1, 1);

    for (int ch = 0; ch < 48; ch++) {
        asm volatile("cp.async.wait_group 1;" ::: "memory");
        __syncthreads();
        int st = ch % 3;
        issue(ch + 2, (ch + 2) % 3);

        uint32_t aBase = sbase + st * STAGE_BYTES;
        uint32_t bBase = aBase + STAGE_BYTES / 2;
        #pragma unroll
        for (int ks = 0; ks < 2; ks++) {
            uint32_t af[2][4], bf[2][4];
            #pragma unroll
            for (int mt = 0; mt < 2; mt++) {
                uint32_t addr = aBase +
                    ((wm + mt * 16 + (lane & 15)) * KST + ks * 16 + (lane >> 4) * 8) * 2;
                asm volatile("ldmatrix.sync.aligned.m8n8.x4.shared.b16 {%0,%1,%2,%3}, [%4];"
                             : "=r"(af[mt][0]), "=r"(af[mt][1]), "=r"(af[mt][2]), "=r"(af[mt][3])
                             : "r"(addr));
            }
            #pragma unroll
            for (int np = 0; np < 2; np++) {
                uint32_t addr = bBase +
                    ((wn + np * 16 + (lane & 15)) * KST + ks * 16 + (lane >> 4) * 8) * 2;
                asm volatile("ldmatrix.sync.aligned.m8n8.x4.shared.b16 {%0,%1,%2,%3}, [%4];"
                             : "=r"(bf[np][0]), "=r"(bf[np][1]), "=r"(bf[np][2]), "=r"(bf[np][3])
                             : "r"(addr));
            }
            #pragma unroll
            for (int mt = 0; mt < 2; mt++) {
                #pragma unroll
                for (int nt = 0; nt < 4; nt++) {
                    uint32_t b0 = bf[nt >> 1][(nt & 1)];
                    uint32_t b1 = bf[nt >> 1][(nt & 1) + 2];
                    asm volatile(
                        "mma.sync.aligned.m16n8k16.row.col.f32.bf16.bf16.f32 "
                        "{%0,%1,%2,%3}, {%4,%5,%6,%7}, {%8,%9}, {%0,%1,%2,%3};"
                        : "+f"(acc[mt][nt][0]), "+f"(acc[mt][nt][1]),
                          "+f"(acc[mt][nt][2]), "+f"(acc[mt][nt][3])
                        : "r"(af[mt][0]), "r"(af[mt][1]), "r"(af[mt][2]), "r"(af[mt][3]),
                          "r"(b0), "r"(b1));
                }
            }
        }
    }

    // epilogue
    #pragma unroll
    for (int mt = 0; mt < 2; mt++) {
        int r = m0 + wm + mt * 16 + (lane >> 2);
        float b0v = bias ? bias[r] : 0.f;
        float b1v = bias ? bias[r + 8] : 0.f;
        #pragma unroll
        for (int nt = 0; nt < 4; nt++) {
            int cn = n0 + wn + nt * 8 + (lane & 3) * 2;
            float2 v0, v1;
            v0.x = acc[mt][nt][0] + b0v;
            v0.y = acc[mt][nt][1] + b0v;
            v1.x = acc[mt][nt][2] + b1v;
            v1.y = acc[mt][nt][3] + b1v;
            *(float2*)(Cb + (size_t)r * NPIX + cn) = v0;
            *(float2*)(Cb + (size_t)(r + 8) * NPIX + cn) = v1;
        }
    }
}

// ---------------- k softmax stats ----------------
__global__ __launch_bounds__(256) void kstats_kernel(const float* __restrict__ qkv,
                                                     float* __restrict__ kmax,
                                                     float* __restrict__ ksum) {
    int idx = blockIdx.x;
    int b = idx >> 9, hc = idx & 511;
    const float* row = qkv + ((size_t)b * QKV_M + 512 + hc) * NPIX;
    int tid = threadIdx.x;
    __shared__ float red[256];
    float m = -1e30f;
    for (int n = tid; n < NPIX; n += 256) m = fmaxf(m, row[n]);
    red[tid] = m;
    __syncthreads();
    for (int st = 128; st > 0; st >>= 1) {
        if (tid < st) red[tid] = fmaxf(red[tid], red[tid + st]);
        __syncthreads();
    }
    m = red[0];
    float s = 0.f;
    for (int n = tid; n < NPIX; n += 256) s += __expf(row[n] - m);
    __syncthreads();
    red[tid] = s;
    __syncthreads();
    for (int st = 128; st > 0; st >>= 1) {
        if (tid < st) red[tid] += red[tid + st];
        __syncthreads();
    }
    if (tid == 0) {
        kmax[idx] = m;
        ksum[idx] = red[0];
    }
}

// ---------------- split-K k^T v ----------------
__global__ __launch_bounds__(256) void kv_kernel(const float* __restrict__ qkv,
                                                 const float* __restrict__ kmax,
                                                 float* __restrict__ part) {
    int bh = blockIdx.y;
    int b = bh >> 3, h = bh & 7;
    int n0 = blockIdx.x * 256;
    const float* kb = qkv + ((size_t)b * QKV_M + 512 + (size_t)h * CH) * NPIX;
    const float* vb = qkv + ((size_t)b * QKV_M + 1024 + (size_t)h * CH) * NPIX;
    __shared__ float Ks[64][33];
    __shared__ float Vs[64][33];
    __shared__ float km[64];
    int tid = threadIdx.x;
    if (tid < 64) km[tid] = kmax[bh * 64 + tid];
    float acc[4][4] = {};
    int ty = tid >> 4, tx = tid & 15;
    for (int nn = 0; nn < 256; nn += 32) {
        __syncthreads();
        #pragma unroll
        for (int l = 0; l < 2; l++) {
            int idx4 = tid + l * 256;
            int r = idx4 >> 3, c4 = (idx4 & 7) << 2;
            float4 kv = *(const float4*)&kb[(size_t)r * NPIX + n0 + nn + c4];
            float mm = km[r];
            Ks[r][c4 + 0] = __expf(kv.x - mm);
            Ks[r][c4 + 1] = __expf(kv.y - mm);
            Ks[r][c4 + 2] = __expf(kv.z - mm);
            Ks[r][c4 + 3] = __expf(kv.w - mm);
            float4 vv = *(const float4*)&vb[(size_t)r * NPIX + n0 + nn + c4];
            Vs[r][c4 + 0] = vv.x;
            Vs[r][c4 + 1] = vv.y;
            Vs[r][c4 + 2] = vv.z;
            Vs[r][c4 + 3] = vv.w;
        }
        __syncthreads();
        #pragma unroll 8
        for (int p = 0; p < 32; p++) {
            float kr[4], vr[4];
            #pragma unroll
            for (int i = 0; i < 4; i++) kr[i] = Ks[ty * 4 + i][p];
            #pragma unroll
            for (int j = 0; j < 4; j++) vr[j] = Vs[tx * 4 + j][p];
            #pragma unroll
            for (int i = 0; i < 4; i++)
                #pragma unroll
                for (int j = 0; j < 4; j++)
                    acc[i][j] = fmaf(kr[i], vr[j], acc[i][j]);
        }
    }
    float* pp = part + ((size_t)blockIdx.x * 64 + bh) * (CH * CH);
    #pragma unroll
    for (int i = 0; i < 4; i++)
        #pragma unroll
        for (int j = 0; j < 4; j++)
            pp[(ty * 4 + i) * 64 + tx * 4 + j] = acc[i][j];
}

// ---------------- combine partials ----------------
__global__ void attn_finalize(const float* __restrict__ part,
                              const float* __restrict__ ksum,
                              float* __restrict__ attn) {
    int idx = blockIdx.x * 256 + threadIdx.x;
    int bh = idx >> 12;
    int cd = idx & 4095;
    int c = cd >> 6;
    float s = 0.f;
    #pragma unroll
    for (int sp = 0; sp < NSPLIT; sp++)
        s += part[((size_t)sp * 64 + bh) * 4096 + cd];
    attn[idx] = s / ksum[bh * 64 + c] * 0.125f;
}

// ---------------- q softmax + out = qs @ attn -> bf16 hi/lo transposed ----------------
__global__ __launch_bounds__(256) void qattn_kernel(const float* __restrict__ qkv,
                                                    const float* __restrict__ attn,
                                                    __nv_bfloat16* __restrict__ ohi,
                                                    __nv_bfloat16* __restrict__ olo) {
    int bh = blockIdx.y;
    int b = bh >> 3, h = bh & 7;
    int n0 = blockIdx.x * 32;
    __shared__ float at[64][64];
    __shared__ float qs[32][65];
    __shared__ float os[64][33];
    int tid = threadIdx.x;

    #pragma unroll
    for (int i = 0; i < 4; i++) {
        int idx4 = tid + i * 256;
        int r = idx4 >> 4, c4 = (idx4 & 15) << 2;
        *(float4*)&at[r][c4] = *(const float4*)&attn[((size_t)bh * 64 + r) * 64 + c4];
    }
    const float* qbase = qkv + ((size_t)b * QKV_M + (size_t)h * CH) * NPIX + n0;
    #pragma unroll
    for (int l = 0; l < 2; l++) {
        int idx4 = tid + l * 256;
        int c = idx4 >> 3;
        int n4 = (idx4 & 7) << 2;
        float4 v = *(const float4*)&qbase[(size_t)c * NPIX + n4];
        qs[n4 + 0][c] = v.x;
        qs[n4 + 1][c] = v.y;
        qs[n4 + 2][c] = v.z;
        qs[n4 + 3][c] = v.w;
    }
    __syncthreads();

    int w = tid >> 5, lane = tid & 31;
    for (int it = 0; it < 4; it++) {
        int nl = w * 4 + it;
        float q0 = qs[nl][lane], q1 = qs[nl][lane + 32];
        float m = fmaxf(q0, q1);
        #pragma unroll
        for (int o = 16; o > 0; o >>= 1) m = fmaxf(m, __shfl_xor_sync(0xffffffffu, m, o));
        float e0 = __expf(q0 - m), e1 = __expf(q1 - m);
        float ssum = e0 + e1;
        #pragma unroll
        for (int o = 16; o > 0; o >>= 1) ssum += __shfl_xor_sync(0xffffffffu, ssum, o);
        float inv = 1.0f / ssum;
        float a0 = 0.f, a1 = 0.f;
        #pragma unroll
        for (int c = 0; c < 32; c++) {
            float ec = __shfl_sync(0xffffffffu, e0, c);
            a0 = fmaf(ec, at[c][lane], a0);
            a1 = fmaf(ec, at[c][lane + 32], a1);
        }
        #pragma unroll
        for (int c = 0; c < 32; c++) {
            float ec = __shfl_sync(0xffffffffu, e1, c);
            a0 = fmaf(ec, at[c + 32][lane], a0);
            a1 = fmaf(ec, at[c + 32][lane + 32], a1);
        }
        os[lane][nl] = a0 * inv;
        os[lane + 32][nl] = a1 * inv;
    }
    __syncthreads();

    size_t obase = ((size_t)b * NPIX + n0) * C + (size_t)h * CH;
    #pragma unroll
    for (int l = 0; l < 4; l++) {
        int p = tid + l * 256;
        int nl = p >> 5;
        int dp = p & 31;
        int d = dp * 2;
        float v0 = os[d][nl], v1 = os[d + 1][nl];
        __nv_bfloat16 h0 = __float2bfloat16_rn(v0);
        __nv_bfloat16 h1 = __float2bfloat16_rn(v1);
        size_t off = obase + (size_t)nl * C + d;
        __nv_bfloat162 hp; hp.x = h0; hp.y = h1;
        *(__nv_bfloat162*)(ohi + off) = hp;
        __nv_bfloat162 lp;
        lp.x = __float2bfloat16_rn(v0 - __bfloat162float(h0));
        lp.y = __float2bfloat16_rn(v1 - __bfloat162float(h1));
        *(__nv_bfloat162*)(olo + off) = lp;
    }
}

// ---------------- final rmsnorm + residual ----------------
__global__ __launch_bounds__(256) void final_kernel(const float* __restrict__ t,
                                                    const float* __restrict__ x,
                                                    const float* __restrict__ g2,
                                                    float* __restrict__ outp) {
    int blk = blockIdx.x;
    int b = blk >> 7;
    int p0 = (blk & 127) << 5;
    int w = threadIdx.x >> 5, j = threadIdx.x & 31;
    const float* tb = t + (size_t)b * C * NPIX + p0 + j;
    float acc = 0.f;
    for (int c = w; c < C; c += 8) {
        float v = tb[(size_t)c * NPIX];
        acc += v * v;
    }
    __shared__ float red[8][32];
    __shared__ float inv[32];
    red[w][j] = acc;
    __syncthreads();
    if (w == 0) {
        float s = 0.f;
        #pragma unroll
        for (int i = 0; i < 8; i++) s += red[i][j];
        float n = fmaxf(sqrtf(s), 1e-12f);
        inv[j] = SQRT_C / n;
    }
    __syncthreads();
    float iv = inv[j];
    const float* xb = x + (size_t)b * C * NPIX + p0 + j;
    float* ob = outp + (size_t)b * C * NPIX + p0 + j;
    for (int c = w; c < C; c += 8) {
        float v = tb[(size_t)c * NPIX];
        ob[(size_t)c * NPIX] = v * iv * g2[c] + xb[(size_t)c * NPIX];
    }
}

// ---------------- launch ----------------
extern "C" void kernel_launch(void* const* d_in, const int* in_sizes, int n_in,
                              void* d_out, int out_size) {
    (void)in_sizes; (void)n_in; (void)out_size;
    const float* x      = (const float*)d_in[0];
    const float* norm_g = (const float*)d_in[1];
    const float* qkv_w  = (const float*)d_in[2];
    const float* ffn_w  = (const float*)d_in[3];
    const float* ffn_b  = (const float*)d_in[4];
    const float* ffn_gn = (const float*)d_in[5];
    float* out = (float*)d_out;

    __nv_bfloat16 *whi, *wlo, *fhi, *flo, *xhi, *xlo, *ohi, *olo;
    float *s, *qkv, *kmax, *ksum, *part, *attn, *ffn;
    cudaGetSymbolAddress((void**)&whi, g_whi);
    cudaGetSymbolAddress((void**)&wlo, g_wlo);
    cudaGetSymbolAddress((void**)&fhi, g_fhi);
    cudaGetSymbolAddress((void**)&flo, g_flo);
    cudaGetSymbolAddress((void**)&s, g_s);
    cudaGetSymbolAddress((void**)&xhi, g_xhi);
    cudaGetSymbolAddress((void**)&xlo, g_xlo);
    cudaGetSymbolAddress((void**)&qkv, g_qkv);
    cudaGetSymbolAddress((void**)&kmax, g_kmax);
    cudaGetSymbolAddress((void**)&ksum, g_ksum);
    cudaGetSymbolAddress((void**)&part, g_part);
    cudaGetSymbolAddress((void**)&attn, g_attn);
    cudaGetSymbolAddress((void**)&ohi, g_ohi);
    cudaGetSymbolAddress((void**)&olo, g_olo);
    cudaGetSymbolAddress((void**)&ffn, g_ffn);

    cudaFuncSetAttribute(hgemm_kernel, cudaFuncAttributeMaxDynamicSharedMemorySize,
                         GEMM_SMEM);

    wsplit_kernel<<<(QKV_M * C) / 256, 256>>>(qkv_w, norm_g, whi, wlo, QKV_M * C);
    wsplit_kernel<<<(C * C) / 256, 256>>>(ffn_w, nullptr, fhi, flo, C * C);
    norm_scale_kernel<<<BATCH * (NPIX / 32), 256>>>(x, s);
    xtrans_kernel<<<dim3(C / 64, NPIX / 32, BATCH), 256>>>(x, s, xhi, xlo);
    hgemm_kernel<<<dim3(32, 12, BATCH), GTHREADS, GEMM_SMEM>>>(whi, wlo, xhi, xlo, qkv,
                                                               QKV_M, nullptr);
    kstats_kernel<<<BATCH * 512, 256>>>(qkv, kmax, ksum);
    kv_kernel<<<dim3(NSPLIT, BATCH * HEADS), 256>>>(qkv, kmax, part);
    attn_finalize<<<(BATCH * HEADS * CH * CH) / 256, 256>>>(part, ksum, attn);
    qattn_kernel<<<dim3(NPIX / 32, BATCH * HEADS), 256>>>(qkv, attn, ohi, olo);
    hgemm_kernel<<<dim3(32, 4, BATCH), GTHREADS, GEMM_SMEM>>>(fhi, flo, ohi, olo, ffn,
                                                              C, ffn_b);
    final_kernel<<<BATCH * (NPIX / 32), 256>>>(ffn, x, ffn_gn, out);
}

// round 5
// speedup vs baseline: 2.0757x; 2.0126x over previous
#include <cuda_runtime.h>
#include <cuda_bf16.h>
#include <cuda_fp16.h>
#include <math.h>
#include <stdint.h>

#define BATCH 8
#define C 512
#define NPIX 4096
#define HEADS 8
#define CH 64
#define QKV_M 1536
#define NSPLIT 16
#define SQRT_C 22.627416997969522f

// GEMM tiling
#define BM 128
#define BN 128
#define KST 40                 // smem row stride in halfs (80B, ldmatrix conflict-free)
#define GTHREADS 512
#define STAGE_BYTES (2 * BM * KST * 2)   // A + B tile per stage
#define GEMM_SMEM (3 * STAGE_BYTES)

// ---------------- device scratch ----------------
__device__ __half g_wh[QKV_M * C];                      // qkv weights (norm_g folded), fp16
__device__ __half g_fh[C * C];                          // ffn weights fp16
__device__ __half g_xhi[(size_t)BATCH * NPIX * C];
__device__ __half g_xlo[(size_t)BATCH * NPIX * C];
__device__ float g_qkv[(size_t)BATCH * QKV_M * NPIX];
__device__ float g_part[(size_t)NSPLIT * BATCH * HEADS * CH * CH];
__device__ float g_spart[(size_t)NSPLIT * BATCH * HEADS * CH];
__device__ float g_attn[BATCH * HEADS * CH * CH];
__device__ __half g_ohi[(size_t)BATCH * NPIX * C];
__device__ __half g_olo[(size_t)BATCH * NPIX * C];
__device__ float g_ffn[(size_t)BATCH * C * NPIX];

__device__ __forceinline__ uint32_t smem_u32(const void* p) {
    uint32_t a;
    asm("{ .reg .u64 t; cvta.to.shared.u64 t, %1; cvt.u32.u64 %0, t; }" : "=r"(a) : "l"(p));
    return a;
}

// ---------------- weight convert (fold norm_g), fp16 ----------------
__global__ void wconv_kernel(const float* __restrict__ w, const float* __restrict__ g,
                             __half* __restrict__ out, int total) {
    int i = blockIdx.x * 256 + threadIdx.x;
    if (i >= total) return;
    float v = w[i];
    if (g) v *= g[i & (C - 1)];
    out[i] = __float2half_rn(v);
}

// ---------------- fused rmsnorm-scale + transpose + fp16 hi/lo split ----------------
// x[b][c][n] -> xt[b][n][c] = x*SQRT_C/||x[:,n]||, as half hi + half lo
__global__ __launch_bounds__(256) void normtrans_kernel(const float* __restrict__ x,
                                                        __half* __restrict__ xhi,
                                                        __half* __restrict__ xlo) {
    int blk = blockIdx.x;
    int b = blk >> 7;
    int n0 = (blk & 127) << 5;       // 32 positions
    int tid = threadIdx.x;
    int w = tid >> 5, j = tid & 31;
    const float* xb = x + (size_t)b * C * NPIX + n0;

    // pass 1: column sumsq
    float acc = 0.f;
    for (int c = w; c < C; c += 8) {
        float v = xb[(size_t)c * NPIX + j];
        acc += v * v;
    }
    __shared__ float red[8][32];
    __shared__ float inv[32];
    red[w][j] = acc;
    __syncthreads();
    if (w == 0) {
        float t = 0.f;
        #pragma unroll
        for (int i = 0; i < 8; i++) t += red[i][j];
        inv[j] = SQRT_C / fmaxf(sqrtf(t), 1e-12f);
    }
    __syncthreads();

    // pass 2: transpose via smem (x re-read from L2), scale, split
    __shared__ float ts[64][33];
    for (int c0 = 0; c0 < C; c0 += 64) {
        __syncthreads();
        #pragma unroll
        for (int l = 0; l < 8; l++) {
            int i = l * 256 + tid;
            int cc = i >> 5, nn = i & 31;
            ts[cc][nn] = xb[(size_t)(c0 + cc) * NPIX + nn];
        }
        __syncthreads();
        #pragma unroll
        for (int l = 0; l < 4; l++) {
            int p = l * 256 + tid;       // 1024 half2 pairs
            int nn = p >> 5;
            int cp = p & 31;
            int c = cp * 2;
            float sc = inv[nn];
            float v0 = ts[c][nn] * sc;
            float v1 = ts[c + 1][nn] * sc;
            __half h0 = __float2half_rn(v0);
            __half h1 = __float2half_rn(v1);
            size_t off = ((size_t)b * NPIX + n0 + nn) * C + c0 + c;
            __half2 hp; hp.x = h0; hp.y = h1;
            *(__half2*)(xhi + off) = hp;
            __half2 lp;
            lp.x = __float2half_rn(v0 - __half2float(h0));
            lp.y = __float2half_rn(v1 - __half2float(h1));
            *(__half2*)(xlo + off) = lp;
        }
    }
}

// ---------------- mma.sync fp16 2-phase GEMM (cp.async, 3-stage) ----------------
// Cout[b][m][n] = sum_c A[m][c] * (Bhi+Blo)[b][n][c]   (K'=1024)
__global__ __launch_bounds__(GTHREADS, 1) void hgemm_kernel(
    const __half* __restrict__ A,
    const __half* __restrict__ Bhi, const __half* __restrict__ Blo,
    float* __restrict__ Cout, int M, const float* __restrict__ bias) {
    extern __shared__ __align__(16) char smem[];
    uint32_t sbase = smem_u32(smem);

    int tid = threadIdx.x, wid = tid >> 5, lane = tid & 31;
    int m0 = blockIdx.y * BM, n0 = blockIdx.x * BN, b = blockIdx.z;
    const __half* Bh = Bhi + (size_t)b * NPIX * C;
    const __half* Bl = Blo + (size_t)b * NPIX * C;
    float* Cb = Cout + (size_t)b * M * NPIX;

    int wm = (wid >> 2) * 32;
    int wn = (wid & 3) * 32;

    int rr = tid >> 2, kc = tid & 3;
    uint32_t dstA = (rr * KST + kc * 8) * 2;
    uint32_t dstB = STAGE_BYTES / 2 + dstA;

    float acc[2][4][4];
    #pragma unroll
    for (int i = 0; i < 2; i++)
        #pragma unroll
        for (int j = 0; j < 4; j++)
            #pragma unroll
            for (int q = 0; q < 4; q++) acc[i][j][q] = 0.f;

    auto issue = [&](int ch, int st) {
        if (ch < 32) {
            int phase = ch >> 4;
            int k0 = (ch & 15) << 5;
            const __half* Bsrc = phase ? Bl : Bh;
            uint32_t da = sbase + st * STAGE_BYTES + dstA;
            uint32_t db = sbase + st * STAGE_BYTES + dstB;
            const __half* ga = A + (size_t)(m0 + rr) * C + k0 + kc * 8;
            const __half* gb = Bsrc + (size_t)(n0 + rr) * C + k0 + kc * 8;
            asm volatile("cp.async.cg.shared.global [%0], [%1], 16;" :: "r"(da), "l"(ga));
            asm volatile("cp.async.cg.shared.global [%0], [%1], 16;" :: "r"(db), "l"(gb));
        }
        asm volatile("cp.async.commit_group;" ::: "memory");
    };

    issue(0, 0);
    issue(1, 1);

    for (int ch = 0; ch < 32; ch++) {
        asm volatile("cp.async.wait_group 1;" ::: "memory");
        __syncthreads();
        int st = ch % 3;
        issue(ch + 2, (ch + 2) % 3);

        uint32_t aBase = sbase + st * STAGE_BYTES;
        uint32_t bBase = aBase + STAGE_BYTES / 2;
        #pragma unroll
        for (int ks = 0; ks < 2; ks++) {
            uint32_t af[2][4], bf[2][4];
            #pragma unroll
            for (int mt = 0; mt < 2; mt++) {
                uint32_t addr = aBase +
                    ((wm + mt * 16 + (lane & 15)) * KST + ks * 16 + (lane >> 4) * 8) * 2;
                asm volatile("ldmatrix.sync.aligned.m8n8.x4.shared.b16 {%0,%1,%2,%3}, [%4];"
                             : "=r"(af[mt][0]), "=r"(af[mt][1]), "=r"(af[mt][2]), "=r"(af[mt][3])
                             : "r"(addr));
            }
            #pragma unroll
            for (int np = 0; np < 2; np++) {
                uint32_t addr = bBase +
                    ((wn + np * 16 + (lane & 15)) * KST + ks * 16 + (lane >> 4) * 8) * 2;
                asm volatile("ldmatrix.sync.aligned.m8n8.x4.shared.b16 {%0,%1,%2,%3}, [%4];"
                             : "=r"(bf[np][0]), "=r"(bf[np][1]), "=r"(bf[np][2]), "=r"(bf[np][3])
                             : "r"(addr));
            }
            #pragma unroll
            for (int mt = 0; mt < 2; mt++) {
                #pragma unroll
                for (int nt = 0; nt < 4; nt++) {
                    uint32_t b0 = bf[nt >> 1][(nt & 1)];
                    uint32_t b1 = bf[nt >> 1][(nt & 1) + 2];
                    asm volatile(
                        "mma.sync.aligned.m16n8k16.row.col.f32.f16.f16.f32 "
                        "{%0,%1,%2,%3}, {%4,%5,%6,%7}, {%8,%9}, {%0,%1,%2,%3};"
                        : "+f"(acc[mt][nt][0]), "+f"(acc[mt][nt][1]),
                          "+f"(acc[mt][nt][2]), "+f"(acc[mt][nt][3])
                        : "r"(af[mt][0]), "r"(af[mt][1]), "r"(af[mt][2]), "r"(af[mt][3]),
                          "r"(b0), "r"(b1));
                }
            }
        }
    }

    #pragma unroll
    for (int mt = 0; mt < 2; mt++) {
        int r = m0 + wm + mt * 16 + (lane >> 2);
        float b0v = bias ? bias[r] : 0.f;
        float b1v = bias ? bias[r + 8] : 0.f;
        #pragma unroll
        for (int nt = 0; nt < 4; nt++) {
            int cn = n0 + wn + nt * 8 + (lane & 3) * 2;
            float2 v0, v1;
            v0.x = acc[mt][nt][0] + b0v;
            v0.y = acc[mt][nt][1] + b0v;
            v1.x = acc[mt][nt][2] + b1v;
            v1.y = acc[mt][nt][3] + b1v;
            *(float2*)(Cb + (size_t)r * NPIX + cn) = v0;
            *(float2*)(Cb + (size_t)(r + 8) * NPIX + cn) = v1;
        }
    }
}

// ---------------- split-K  exp(k)^T v  + ksum (no max needed: |k| <= ~12) ----------------
__global__ __launch_bounds__(256) void kv_kernel(const float* __restrict__ qkv,
                                                 float* __restrict__ part,
                                                 float* __restrict__ spart) {
    int bh = blockIdx.y;
    int b = bh >> 3, h = bh & 7;
    int n0 = blockIdx.x * 256;
    const float* kb = qkv + ((size_t)b * QKV_M + 512 + (size_t)h * CH) * NPIX;
    const float* vb = qkv + ((size_t)b * QKV_M + 1024 + (size_t)h * CH) * NPIX;
    __shared__ float Ks[64][33];
    __shared__ float Vs[64][33];
    int tid = threadIdx.x;
    float acc[4][4] = {};
    float ssum[4] = {0.f, 0.f, 0.f, 0.f};
    int ty = tid >> 4, tx = tid & 15;
    for (int nn = 0; nn < 256; nn += 32) {
        __syncthreads();
        #pragma unroll
        for (int l = 0; l < 2; l++) {
            int idx4 = tid + l * 256;
            int r = idx4 >> 3, c4 = (idx4 & 7) << 2;
            float4 kv = *(const float4*)&kb[(size_t)r * NPIX + n0 + nn + c4];
            Ks[r][c4 + 0] = __expf(kv.x);
            Ks[r][c4 + 1] = __expf(kv.y);
            Ks[r][c4 + 2] = __expf(kv.z);
            Ks[r][c4 + 3] = __expf(kv.w);
            float4 vv = *(const float4*)&vb[(size_t)r * NPIX + n0 + nn + c4];
            Vs[r][c4 + 0] = vv.x;
            Vs[r][c4 + 1] = vv.y;
            Vs[r][c4 + 2] = vv.z;
            Vs[r][c4 + 3] = vv.w;
        }
        __syncthreads();
        #pragma unroll 8
        for (int p = 0; p < 32; p++) {
            float kr[4], vr[4];
            #pragma unroll
            for (int i = 0; i < 4; i++) kr[i] = Ks[ty * 4 + i][p];
            #pragma unroll
            for (int j = 0; j < 4; j++) vr[j] = Vs[tx * 4 + j][p];
            if (tx == 0) {
                #pragma unroll
                for (int i = 0; i < 4; i++) ssum[i] += kr[i];
            }
            #pragma unroll
            for (int i = 0; i < 4; i++)
                #pragma unroll
                for (int j = 0; j < 4; j++)
                    acc[i][j] = fmaf(kr[i], vr[j], acc[i][j]);
        }
    }
    float* pp = part + ((size_t)blockIdx.x * 64 + bh) * (CH * CH);
    #pragma unroll
    for (int i = 0; i < 4; i++)
        #pragma unroll
        for (int j = 0; j < 4; j++)
            pp[(ty * 4 + i) * 64 + tx * 4 + j] = acc[i][j];
    if (tx == 0) {
        float* sp = spart + ((size_t)blockIdx.x * 64 + bh) * CH;
        #pragma unroll
        for (int i = 0; i < 4; i++) sp[ty * 4 + i] = ssum[i];
    }
}

// ---------------- combine partials ----------------
__global__ void attn_finalize(const float* __restrict__ part,
                              const float* __restrict__ spart,
                              float* __restrict__ attn) {
    int idx = blockIdx.x * 256 + threadIdx.x;
    int bh = idx >> 12;
    int cd = idx & 4095;
    int c = cd >> 6;
    float s = 0.f, ks = 0.f;
    #pragma unroll
    for (int sp = 0; sp < NSPLIT; sp++) {
        s += part[((size_t)sp * 64 + bh) * 4096 + cd];
        ks += spart[((size_t)sp * 64 + bh) * CH + c];
    }
    attn[idx] = s / ks * 0.125f;
}

// ---------------- q softmax + out = qs @ attn -> fp16 hi/lo transposed ----------------
__global__ __launch_bounds__(256) void qattn_kernel(const float* __restrict__ qkv,
                                                    const float* __restrict__ attn,
                                                    __half* __restrict__ ohi,
                                                    __half* __restrict__ olo) {
    int bh = blockIdx.y;
    int b = bh >> 3, h = bh & 7;
    int n0 = blockIdx.x * 32;
    __shared__ float at[64][64];
    __shared__ float qs[32][65];
    __shared__ float os[64][33];
    int tid = threadIdx.x;

    #pragma unroll
    for (int i = 0; i < 4; i++) {
        int idx4 = tid + i * 256;
        int r = idx4 >> 4, c4 = (idx4 & 15) << 2;
        *(float4*)&at[r][c4] = *(const float4*)&attn[((size_t)bh * 64 + r) * 64 + c4];
    }
    const float* qbase = qkv + ((size_t)b * QKV_M + (size_t)h * CH) * NPIX + n0;
    #pragma unroll
    for (int l = 0; l < 2; l++) {
        int idx4 = tid + l * 256;
        int c = idx4 >> 3;
        int n4 = (idx4 & 7) << 2;
        float4 v = *(const float4*)&qbase[(size_t)c * NPIX + n4];
        qs[n4 + 0][c] = v.x;
        qs[n4 + 1][c] = v.y;
        qs[n4 + 2][c] = v.z;
        qs[n4 + 3][c] = v.w;
    }
    __syncthreads();

    int w = tid >> 5, lane = tid & 31;
    for (int it = 0; it < 4; it++) {
        int nl = w * 4 + it;
        float e0 = __expf(qs[nl][lane]);
        float e1 = __expf(qs[nl][lane + 32]);
        float ssum = e0 + e1;
        #pragma unroll
        for (int o = 16; o > 0; o >>= 1) ssum += __shfl_xor_sync(0xffffffffu, ssum, o);
        float inv = 1.0f / ssum;
        float a0 = 0.f, a1 = 0.f;
        #pragma unroll
        for (int c = 0; c < 32; c++) {
            float ec = __shfl_sync(0xffffffffu, e0, c);
            a0 = fmaf(ec, at[c][lane], a0);
            a1 = fmaf(ec, at[c][lane + 32], a1);
        }
        #pragma unroll
        for (int c = 0; c < 32; c++) {
            float ec = __shfl_sync(0xffffffffu, e1, c);
            a0 = fmaf(ec, at[c + 32][lane], a0);
            a1 = fmaf(ec, at[c + 32][lane + 32], a1);
        }
        os[lane][nl] = a0 * inv;
        os[lane + 32][nl] = a1 * inv;
    }
    __syncthreads();

    size_t obase = ((size_t)b * NPIX + n0) * C + (size_t)h * CH;
    #pragma unroll
    for (int l = 0; l < 4; l++) {
        int p = tid + l * 256;
        int nl = p >> 5;
        int dp = p & 31;
        int d = dp * 2;
        float v0 = os[d][nl], v1 = os[d + 1][nl];
        __half h0 = __float2half_rn(v0);
        __half h1 = __float2half_rn(v1);
        size_t off = obase + (size_t)nl * C + d;
        __half2 hp; hp.x = h0; hp.y = h1;
        *(__half2*)(ohi + off) = hp;
        __half2 lp;
        lp.x = __float2half_rn(v0 - __half2float(h0));
        lp.y = __float2half_rn(v1 - __half2float(h1));
        *(__half2*)(olo + off) = lp;
    }
}

// ---------------- final rmsnorm + residual ----------------
__global__ __launch_bounds__(256) void final_kernel(const float* __restrict__ t,
                                                    const float* __restrict__ x,
                                                    const float* __restrict__ g2,
                                                    float* __restrict__ outp) {
    int blk = blockIdx.x;
    int b = blk >> 7;
    int p0 = (blk & 127) << 5;
    int w = threadIdx.x >> 5, j = threadIdx.x & 31;
    const float* tb = t + (size_t)b * C * NPIX + p0 + j;
    float acc = 0.f;
    for (int c = w; c < C; c += 8) {
        float v = tb[(size_t)c * NPIX];
        acc += v * v;
    }
    __shared__ float red[8][32];
    __shared__ float inv[32];
    red[w][j] = acc;
    __syncthreads();
    if (w == 0) {
        float s = 0.f;
        #pragma unroll
        for (int i = 0; i < 8; i++) s += red[i][j];
        float n = fmaxf(sqrtf(s), 1e-12f);
        inv[j] = SQRT_C / n;
    }
    __syncthreads();
    float iv = inv[j];
    const float* xb = x + (size_t)b * C * NPIX + p0 + j;
    float* ob = outp + (size_t)b * C * NPIX + p0 + j;
    for (int c = w; c < C; c += 8) {
        float v = tb[(size_t)c * NPIX];
        ob[(size_t)c * NPIX] = v * iv * g2[c] + xb[(size_t)c * NPIX];
    }
}

// ---------------- launch ----------------
extern "C" void kernel_launch(void* const* d_in, const int* in_sizes, int n_in,
                              void* d_out, int out_size) {
    (void)in_sizes; (void)n_in; (void)out_size;
    const float* x      = (const float*)d_in[0];
    const float* norm_g = (const float*)d_in[1];
    const float* qkv_w  = (const float*)d_in[2];
    const float* ffn_w  = (const float*)d_in[3];
    const float* ffn_b  = (const float*)d_in[4];
    const float* ffn_gn = (const float*)d_in[5];
    float* out = (float*)d_out;

    __half *wh, *fh, *xhi, *xlo, *ohi, *olo;
    float *qkv, *part, *spart, *attn, *ffn;
    cudaGetSymbolAddress((void**)&wh, g_wh);
    cudaGetSymbolAddress((void**)&fh, g_fh);
    cudaGetSymbolAddress((void**)&xhi, g_xhi);
    cudaGetSymbolAddress((void**)&xlo, g_xlo);
    cudaGetSymbolAddress((void**)&qkv, g_qkv);
    cudaGetSymbolAddress((void**)&part, g_part);
    cudaGetSymbolAddress((void**)&spart, g_spart);
    cudaGetSymbolAddress((void**)&attn, g_attn);
    cudaGetSymbolAddress((void**)&ohi, g_ohi);
    cudaGetSymbolAddress((void**)&olo, g_olo);
    cudaGetSymbolAddress((void**)&ffn, g_ffn);

    cudaFuncSetAttribute(hgemm_kernel, cudaFuncAttributeMaxDynamicSharedMemorySize,
                         GEMM_SMEM);

    wconv_kernel<<<(QKV_M * C) / 256, 256>>>(qkv_w, norm_g, wh, QKV_M * C);
    wconv_kernel<<<(C * C) / 256, 256>>>(ffn_w, nullptr, fh, C * C);
    normtrans_kernel<<<BATCH * (NPIX / 32), 256>>>(x, xhi, xlo);
    hgemm_kernel<<<dim3(32, 12, BATCH), GTHREADS, GEMM_SMEM>>>(wh, xhi, xlo, qkv,
                                                               QKV_M, nullptr);
    kv_kernel<<<dim3(NSPLIT, BATCH * HEADS), 256>>>(qkv, part, spart);
    attn_finalize<<<(BATCH * HEADS * CH * CH) / 256, 256>>>(part, spart, attn);
    qattn_kernel<<<dim3(NPIX / 32, BATCH * HEADS), 256>>>(qkv, attn, ohi, olo);
    hgemm_kernel<<<dim3(32, 4, BATCH), GTHREADS, GEMM_SMEM>>>(fh, ohi, olo, ffn,
                                                              C, ffn_b);
    final_kernel<<<BATCH * (NPIX / 32), 256>>>(ffn, x, ffn_gn, out);
}